// round 13
// baseline (speedup 1.0000x reference)
#include <cuda_runtime.h>
#include <cstdint>

// Problem dims
static constexpr int Bn = 8, Tn = 256, Un = 64, Dn = 512, Vn = 1024;
// Tiling
static constexpr int MT = 128;             // CTA m-tile
static constexpr int NT = 128;             // CTA n-tile
static constexpr int KC = 32;              // k-chunk (floats)
static constexpr int NKC = Dn / KC;        // 16
static constexpr int M_TOTAL = Bn * Tn * Un;        // 131072
static constexpr int MTILES  = M_TOTAL / MT;        // 1024
static constexpr int NTILES  = Vn / NT;             // 8
static constexpr int MAIN_OUT = M_TOTAL * Vn;       // 134217728

// Padded smem row stride (floats): 36 -> 144B rows (16B aligned), ldmatrix rows
// land on distinct banks (4*row offset), frag v4 loads conflict-light.
static constexpr int PADS = 36;
static constexpr int BUF_F = 128 * PADS;            // floats per stage buffer (4608)
static constexpr int SMEM_TOTAL = 4 * BUF_F * 4;    // 2 A stages + 2 W stages = 73728 B

// W pre-converted to tf32 bits, blocked [nt][kc][row(128)][col(32)], with the
// 32-k chunk K-PERMUTED per 16-k half: pos(kk) = 4*(kk&3) + (kk>>2). This makes
// the runtime B-fragment load a single LDS.128 covering two ks-steps.
__device__ uint32_t g_W[(size_t)NTILES * NKC * MT * KC];   // 2 MB

// ---------------- helpers ----------------
__device__ __forceinline__ uint32_t smem_u32(const void* p) {
    uint32_t a;
    asm("{ .reg .u64 t; cvta.to.shared.u64 t, %1; cvt.u32.u64 %0, t; }" : "=r"(a) : "l"(p));
    return a;
}
__device__ __forceinline__ uint32_t f32_to_tf32(float f) {
    uint32_t r;
    asm("cvt.rna.tf32.f32 %0, %1;" : "=r"(r) : "f"(f));
    return r;
}
__device__ __forceinline__ void cp_async16(uint32_t smem_addr, const void* gptr) {
    asm volatile("cp.async.cg.shared.global [%0], [%1], 16;"
                 :: "r"(smem_addr), "l"(gptr) : "memory");
}
__device__ __forceinline__ void cp_commit() {
    asm volatile("cp.async.commit_group;" ::: "memory");
}
__device__ __forceinline__ void cp_wait_all() {
    asm volatile("cp.async.wait_all;" ::: "memory");
}
// m16n8k8 tf32 MMA: A row-major (16x8), B col-major (8x8), fp32 accumulate.
__device__ __forceinline__ void mma_tf32(float* d, const uint32_t* a, uint32_t b0, uint32_t b1) {
    asm volatile(
        "mma.sync.aligned.m16n8k8.row.col.f32.tf32.tf32.f32 "
        "{%0,%1,%2,%3}, {%4,%5,%6,%7}, {%8,%9}, {%0,%1,%2,%3};"
        : "+f"(d[0]), "+f"(d[1]), "+f"(d[2]), "+f"(d[3])
        : "r"(a[0]), "r"(a[1]), "r"(a[2]), "r"(a[3]), "r"(b0), "r"(b1));
}
// ldmatrix x4 on 8x4 f32 blocks (b16 form; 16B rows). Gives the exact tf32 A frag.
__device__ __forceinline__ void ldmat_x4(uint32_t* r, uint32_t addr) {
    asm volatile("ldmatrix.sync.aligned.m8n8.x4.shared.b16 {%0,%1,%2,%3}, [%4];"
                 : "=r"(r[0]), "=r"(r[1]), "=r"(r[2]), "=r"(r[3]) : "r"(addr));
}
__device__ __forceinline__ void lds128(uint32_t& a, uint32_t& b, uint32_t& c, uint32_t& d,
                                       uint32_t addr) {
    asm volatile("ld.shared.v4.b32 {%0,%1,%2,%3}, [%4];"
                 : "=r"(a), "=r"(b), "=r"(c), "=r"(d) : "r"(addr));
}

// ---------------- prep kernel: W -> tf32 bits, blocked + k-permuted ----------------
__global__ void prep_w_kernel(const float* __restrict__ W) {
    int idx = blockIdx.x * blockDim.x + threadIdx.x;
    if (idx >= Vn * Dn) return;
    int v = idx >> 9;          // / Dn
    int d = idx & 511;
    int nt  = v >> 7;          // / NT
    int row = v & 127;
    int kc  = d >> 5;          // / KC
    int col = d & 31;          // k within chunk
    int half = col >> 4;
    int kk   = col & 15;
    int scol = (half << 4) | (((kk & 3) << 2) | (kk >> 2));   // permuted position
    g_W[(((size_t)nt * NKC + kc) << 12) + (row << 5) + scol] = f32_to_tf32(W[idx]);
}

// ---------------- main kernel ----------------
__global__ __launch_bounds__(256, 2)
void joiner_mma_kernel(const float* __restrict__ src,   // (B*T, D)
                       const float* __restrict__ tgt,   // (B*U, D)
                       const float* __restrict__ bias,  // (V,)
                       float* __restrict__ out)         // (B*T*U, V)
{
    extern __shared__ __align__(16) float smf[];
    // smem: A stage0 | A stage1 | W stage0 | W stage1, each BUF_F floats
    float* As_[2] = { smf,              smf + BUF_F };
    float* Ws_[2] = { smf + 2 * BUF_F,  smf + 3 * BUF_F };

    const int tid  = threadIdx.x;
    const int wid  = tid >> 5;
    const int lane = tid & 31;
    const int gid  = lane >> 2;   // 0..7
    const int tig  = lane & 3;    // 0..3
    const int warp_m = wid & 3;   // 4 m-warps (32 rows each)
    const int warp_n = wid >> 2;  // 2 n-warps (64 cols each)

    const int mt = blockIdx.x;
    const int nt = blockIdx.y;
    const int g0 = mt * 2;        // first of two 64-row u-groups; g = flattened b*T+t
    const int bb = g0 >> 8;       // batch (T = 256)

    // Per-thread copy-slot offsets (4 slots of 16 B; 1024 slots cover a 16 KB chunk)
    int off_src[4], off_tgt[4], sts_off[4], wsrc_off[4];
    uint32_t wdst_addr[4];
#pragma unroll
    for (int i = 0; i < 4; i++) {
        const int sidx = tid + i * 256;       // 0..1023
        const int row  = sidx >> 3;           // 0..127
        const int seg  = sidx & 7;            // 0..7 (4-float segment)
        const int g    = g0 + (row >> 6);
        const int u    = row & 63;
        off_src[i] = g * Dn + seg * 4;                    // + d0
        off_tgt[i] = (bb * Un + u) * Dn + seg * 4;        // + d0
        sts_off[i] = row * PADS + seg * 4;                // smem float index
        wsrc_off[i] = sidx * 4;                           // float index within W chunk
        wdst_addr[i] = smem_u32(Ws_[0] + sts_off[i]);     // stage-0 byte address
    }
    const uint32_t wstage_bytes = BUF_F * 4;

    // ldmatrix lane offset (bytes) within an A (rb, ks) block set
    const int quad = lane >> 3, r8 = lane & 7;
    const uint32_t a_lane_off = (uint32_t)((((quad & 1) * 8 + r8) * PADS + (quad >> 1) * 4) * 4);
    const uint32_t a_base[2] = { smem_u32(As_[0]), smem_u32(As_[1]) };
    const uint32_t w_base[2] = { smem_u32(Ws_[0]), smem_u32(Ws_[1]) };

    float acc[2][8][4];
#pragma unroll
    for (int a = 0; a < 2; a++)
#pragma unroll
        for (int b = 0; b < 8; b++)
#pragma unroll
            for (int c = 0; c < 4; c++) acc[a][b][c] = 0.0f;

    const size_t wchunk_base = ((size_t)nt * NKC) << 12;   // float idx of (nt, kc=0)

    // ---- Prologue: stage 0 for chunk 0 ----
#pragma unroll
    for (int i = 0; i < 4; i++)
        cp_async16(wdst_addr[i], g_W + wchunk_base + wsrc_off[i]);
    cp_commit();
#pragma unroll
    for (int i = 0; i < 4; i++) {
        const float4 sv = *(const float4*)(src + off_src[i]);
        const float4 tv = *(const float4*)(tgt + off_tgt[i]);
        uint4 o;
        o.x = f32_to_tf32(fmaxf(sv.x + tv.x, 0.0f));
        o.y = f32_to_tf32(fmaxf(sv.y + tv.y, 0.0f));
        o.z = f32_to_tf32(fmaxf(sv.z + tv.z, 0.0f));
        o.w = f32_to_tf32(fmaxf(sv.w + tv.w, 0.0f));
        *(uint4*)(As_[0] + sts_off[i]) = o;
    }
    cp_wait_all();
    __syncthreads();

    // ---- Main loop over 16 k-chunks, double buffered ----
#pragma unroll 1
    for (int kc = 0; kc < NKC; kc++) {
        const int cur = kc & 1;
        const int nxt = cur ^ 1;
        const bool pf = (kc + 1) < NKC;

        float4 s4[4], t4[4];
        if (pf) {
            const size_t wb = wchunk_base + ((size_t)(kc + 1) << 12);
#pragma unroll
            for (int i = 0; i < 4; i++)
                cp_async16(wdst_addr[i] + nxt * wstage_bytes, g_W + wb + wsrc_off[i]);
            cp_commit();
            const int d0 = (kc + 1) * KC;
#pragma unroll
            for (int i = 0; i < 4; i++) {
                s4[i] = *(const float4*)(src + off_src[i] + d0);
                t4[i] = *(const float4*)(tgt + off_tgt[i] + d0);
            }
        }

        // ---- Compute on current buffers: 64 MMA, 8 ldmatrix, 16 LDS.128 ----
        const uint32_t Asb = a_base[cur];
        const uint32_t Wsb = w_base[cur];
#pragma unroll
        for (int h = 0; h < 2; h++) {            // two 16-k halves
            uint32_t afr[2][2][4];               // [ksub][tm][4]
#pragma unroll
            for (int tm = 0; tm < 2; tm++) {
                const int rb = warp_m * 32 + tm * 16;
#pragma unroll
                for (int s = 0; s < 2; s++) {
                    const int ks = h * 2 + s;
                    ldmat_x4(afr[s][tm], Asb + a_lane_off + (uint32_t)((rb * PADS + ks * 8) * 4));
                }
            }
#pragma unroll
            for (int tn = 0; tn < 8; tn++) {
                const int nr = warp_n * 64 + tn * 8 + gid;
                uint32_t b0, b1, b2, b3;
                lds128(b0, b1, b2, b3, Wsb + (uint32_t)((nr * PADS + h * 16 + tig * 4) * 4));
                mma_tf32(acc[0][tn], afr[0][0], b0, b1);
                mma_tf32(acc[1][tn], afr[0][1], b0, b1);
                mma_tf32(acc[0][tn], afr[1][0], b2, b3);
                mma_tf32(acc[1][tn], afr[1][1], b2, b3);
            }
        }

        if (pf) {
#pragma unroll
            for (int i = 0; i < 4; i++) {
                uint4 o;
                o.x = f32_to_tf32(fmaxf(s4[i].x + t4[i].x, 0.0f));
                o.y = f32_to_tf32(fmaxf(s4[i].y + t4[i].y, 0.0f));
                o.z = f32_to_tf32(fmaxf(s4[i].z + t4[i].z, 0.0f));
                o.w = f32_to_tf32(fmaxf(s4[i].w + t4[i].w, 0.0f));
                *(uint4*)(As_[nxt] + sts_off[i]) = o;
            }
            cp_wait_all();
        }
        __syncthreads();
    }

    // ---- Epilogue: registers -> global with bias ----
    const int mbase = mt * MT + warp_m * 32;
    const int nbase = nt * NT + warp_n * 64;
#pragma unroll
    for (int tn = 0; tn < 8; tn++) {
        const int c = nbase + tn * 8 + 2 * tig;
        const float2 bz = *(const float2*)(bias + c);
#pragma unroll
        for (int tm = 0; tm < 2; tm++) {
            const int r0 = mbase + tm * 16 + gid;
            float2 v0, v1;
            v0.x = acc[tm][tn][0] + bz.x;  v0.y = acc[tm][tn][1] + bz.y;
            v1.x = acc[tm][tn][2] + bz.x;  v1.y = acc[tm][tn][3] + bz.y;
            *(float2*)(out + (size_t)r0 * Vn + c) = v0;
            *(float2*)(out + (size_t)(r0 + 8) * Vn + c) = v1;
        }
    }
}

// Pass-through lengths if the harness concatenates the output tuple.
__global__ void tail_kernel(const int* __restrict__ sl, const int* __restrict__ tl,
                            float* __restrict__ dst, int n) {
    int i = threadIdx.x;
    if (i < n) {
        float v = 0.0f;
        if (i < 8) v = (float)sl[i];
        else if (i < 16) v = (float)tl[i - 8];
        dst[i] = v;
    }
}

extern "C" void kernel_launch(void* const* d_in, const int* in_sizes, int n_in,
                              void* d_out, int out_size) {
    const float* src  = (const float*)d_in[0];   // (B,T,D) f32
    const int*   slen = (const int*)d_in[1];     // (B,) i32
    const float* tgt  = (const float*)d_in[2];   // (B,U,D) f32
    const int*   tlen = (const int*)d_in[3];     // (B,) i32
    const float* W    = (const float*)d_in[4];   // (V,D) f32
    const float* bias = (const float*)d_in[5];   // (V,) f32
    float* out = (float*)d_out;

    (void)in_sizes; (void)n_in;

    // 1) Convert W -> tf32 bits in blocked, k-permuted layout (~4 MB traffic)
    prep_w_kernel<<<(Vn * Dn + 255) / 256, 256>>>(W);

    // 2) Fused relu-add GEMM (mma.sync tf32, ldmatrix A frags, v4 B frags)
    cudaFuncSetAttribute(joiner_mma_kernel, cudaFuncAttributeMaxDynamicSharedMemorySize,
                         SMEM_TOTAL);
    dim3 grid(MTILES, NTILES);
    joiner_mma_kernel<<<grid, 256, SMEM_TOTAL>>>(src, tgt, bias, out);

    // 3) Optional pass-through lengths
    int extra = out_size - MAIN_OUT;
    if (extra > 0) {
        if (extra > 32) extra = 32;
        tail_kernel<<<1, 32>>>(slen, tlen, out + MAIN_OUT, extra);
    }
}

// round 14
// speedup vs baseline: 2.5924x; 2.5924x over previous
#include <cuda_runtime.h>
#include <cuda_fp16.h>
#include <cstdint>

// Problem dims
static constexpr int Bn = 8, Tn = 256, Un = 64, Dn = 512, Vn = 1024;
// Tiling
static constexpr int MT = 128;             // CTA m-tile
static constexpr int NT = 128;             // CTA n-tile
static constexpr int KC = 32;              // k-chunk (elements)
static constexpr int KP = KC / 2;          // 16 half2 pairs per row-chunk
static constexpr int NKC = Dn / KC;        // 16
static constexpr int M_TOTAL = Bn * Tn * Un;        // 131072
static constexpr int MTILES  = M_TOTAL / MT;        // 1024
static constexpr int NTILES  = Vn / NT;             // 8
static constexpr int MAIN_OUT = M_TOTAL * Vn;       // 134217728

// Smem row stride in u32 (half2) units: 20 -> 80B rows, 16B aligned.
// Fragment loads: bank = (20*row + col) % 32; over a warp (rowsel=gid, col=tig[+4])
// 20*gid mod 32 = {0,20,8,28,16,4,24,12} (a full 4-spaced set) + tig -> 32 distinct banks.
static constexpr int P = 20;
static constexpr int BUF_U = 128 * P;               // u32 per stage buffer (2560)
static constexpr int SMEM_TOTAL = 4 * BUF_U * 4;    // A0,A1,W0,W1 = 40960 B

// W pre-packed to half2, blocked [nt][kc][n(128)][kpair(16)] contiguous (1 MB).
__device__ uint32_t g_W[(size_t)NTILES * NKC * MT * KP];

// ---------------- helpers ----------------
__device__ __forceinline__ uint32_t smem_u32(const void* p) {
    uint32_t a;
    asm("{ .reg .u64 t; cvta.to.shared.u64 t, %1; cvt.u32.u64 %0, t; }" : "=r"(a) : "l"(p));
    return a;
}
__device__ __forceinline__ uint32_t pack_h2(float x, float y) {
    __half2 h = __floats2half2_rn(x, y);
    return *reinterpret_cast<uint32_t*>(&h);
}
__device__ __forceinline__ void cp_async16(uint32_t smem_addr, const void* gptr) {
    asm volatile("cp.async.cg.shared.global [%0], [%1], 16;"
                 :: "r"(smem_addr), "l"(gptr) : "memory");
}
__device__ __forceinline__ void cp_commit() {
    asm volatile("cp.async.commit_group;" ::: "memory");
}
__device__ __forceinline__ void cp_wait_all() {
    asm volatile("cp.async.wait_all;" ::: "memory");
}
// m16n8k16 fp16 MMA, fp32 accumulate. A row-major, B col-major.
__device__ __forceinline__ void mma_f16(float* d, const uint32_t* a, uint32_t b0, uint32_t b1) {
    asm volatile(
        "mma.sync.aligned.m16n8k16.row.col.f32.f16.f16.f32 "
        "{%0,%1,%2,%3}, {%4,%5,%6,%7}, {%8,%9}, {%0,%1,%2,%3};"
        : "+f"(d[0]), "+f"(d[1]), "+f"(d[2]), "+f"(d[3])
        : "r"(a[0]), "r"(a[1]), "r"(a[2]), "r"(a[3]), "r"(b0), "r"(b1));
}

// ---------------- prep kernel: W -> half2 pairs, blocked layout ----------------
__global__ void prep_w_kernel(const float* __restrict__ W) {
    int idx = blockIdx.x * blockDim.x + threadIdx.x;
    if (idx >= Vn * Dn / 2) return;
    int v = idx >> 8;          // / (Dn/2)
    int p = idx & 255;         // pair index within row
    const float2 w2 = *(const float2*)(W + (size_t)v * Dn + p * 2);
    int nt = v >> 7;           // / NT
    int n  = v & 127;
    int kc = p >> 4;           // / KP
    int kp = p & 15;
    g_W[(((size_t)nt * NKC + kc) << 11) + (n << 4) + kp] = pack_h2(w2.x, w2.y);
}

// ---------------- main kernel ----------------
__global__ __launch_bounds__(256, 2)
void joiner_mma_kernel(const float* __restrict__ src,   // (B*T, D)
                       const float* __restrict__ tgt,   // (B*U, D)
                       const float* __restrict__ bias,  // (V,)
                       float* __restrict__ out)         // (B*T*U, V)
{
    extern __shared__ __align__(16) uint32_t smu[];
    uint32_t* As_[2] = { smu,              smu + BUF_U };
    uint32_t* Ws_[2] = { smu + 2 * BUF_U,  smu + 3 * BUF_U };

    const int tid  = threadIdx.x;
    const int wid  = tid >> 5;
    const int lane = tid & 31;
    const int gid  = lane >> 2;   // 0..7
    const int tig  = lane & 3;    // 0..3
    const int warp_m = wid & 3;   // 4 m-warps (32 rows each)
    const int warp_n = wid >> 2;  // 2 n-warps (64 cols each)

    const int mt = blockIdx.x;
    const int nt = blockIdx.y;
    const int g0 = mt * 2;        // first of two 64-row u-groups; g = flattened b*T+t
    const int bb = g0 >> 8;       // batch (T = 256)

    // Per-thread slots: A chunk = 512x16B slots, W chunk = 512x16B slots; 2 each.
    int off_src[2], off_tgt[2], a_sts[2], w_src[2];
    uint32_t w_dst[2];
#pragma unroll
    for (int i = 0; i < 2; i++) {
        const int sidx = tid + i * 256;      // 0..511
        const int row  = sidx >> 2;          // 0..127
        const int seg  = sidx & 3;           // 0..3 (8 floats / 4 half2 each)
        const int g    = g0 + (row >> 6);
        const int u    = row & 63;
        off_src[i] = g * Dn + seg * 8;                 // + d0
        off_tgt[i] = (bb * Un + u) * Dn + seg * 8;     // + d0
        a_sts[i]  = row * P + seg * 4;                 // u32 index
        w_src[i]  = (sidx) * 4;                        // u32 index within W chunk
        w_dst[i]  = smem_u32(Ws_[0] + row * P + seg * 4);
    }
    const uint32_t wstage_bytes = BUF_U * 4;

    float acc[2][8][4];
#pragma unroll
    for (int a = 0; a < 2; a++)
#pragma unroll
        for (int b = 0; b < 8; b++)
#pragma unroll
            for (int c = 0; c < 4; c++) acc[a][b][c] = 0.0f;

    const size_t wchunk_base = ((size_t)nt * NKC) << 11;   // u32 idx of (nt, kc=0)

    // ---- Prologue: stage 0 for chunk 0 ----
#pragma unroll
    for (int i = 0; i < 2; i++)
        cp_async16(w_dst[i], g_W + wchunk_base + w_src[i]);
    cp_commit();
#pragma unroll
    for (int i = 0; i < 2; i++) {
        const float4 s0 = *(const float4*)(src + off_src[i]);
        const float4 s1 = *(const float4*)(src + off_src[i] + 4);
        const float4 t0 = *(const float4*)(tgt + off_tgt[i]);
        const float4 t1 = *(const float4*)(tgt + off_tgt[i] + 4);
        uint4 o;
        o.x = pack_h2(fmaxf(s0.x + t0.x, 0.0f), fmaxf(s0.y + t0.y, 0.0f));
        o.y = pack_h2(fmaxf(s0.z + t0.z, 0.0f), fmaxf(s0.w + t0.w, 0.0f));
        o.z = pack_h2(fmaxf(s1.x + t1.x, 0.0f), fmaxf(s1.y + t1.y, 0.0f));
        o.w = pack_h2(fmaxf(s1.z + t1.z, 0.0f), fmaxf(s1.w + t1.w, 0.0f));
        *(uint4*)(As_[0] + a_sts[i]) = o;
    }
    cp_wait_all();
    __syncthreads();

    // ---- Main loop over 16 k-chunks, double buffered ----
#pragma unroll 1
    for (int kc = 0; kc < NKC; kc++) {
        const int cur = kc & 1;
        const int nxt = cur ^ 1;
        const bool pf = (kc + 1) < NKC;

        float4 s4[2][2], t4[2][2];
        if (pf) {
            const size_t wb = wchunk_base + ((size_t)(kc + 1) << 11);
#pragma unroll
            for (int i = 0; i < 2; i++)
                cp_async16(w_dst[i] + nxt * wstage_bytes, g_W + wb + w_src[i]);
            cp_commit();
            const int d0 = (kc + 1) * KC;
#pragma unroll
            for (int i = 0; i < 2; i++) {
                s4[i][0] = *(const float4*)(src + off_src[i] + d0);
                s4[i][1] = *(const float4*)(src + off_src[i] + d0 + 4);
                t4[i][0] = *(const float4*)(tgt + off_tgt[i] + d0);
                t4[i][1] = *(const float4*)(tgt + off_tgt[i] + d0 + 4);
            }
        }

        // ---- Compute on current buffers: 32 MMA, 16 A-LDS, 32 B-LDS (all conflict-free)
        const uint32_t* As = As_[cur];
        const uint32_t* Ws = Ws_[cur];
#pragma unroll
        for (int ks = 0; ks < 2; ks++) {       // two k16 steps per 32-k chunk
            const int ko = ks * 8;             // pair-column base
            uint32_t afr[2][4];
#pragma unroll
            for (int tm = 0; tm < 2; tm++) {
                const int rb = warp_m * 32 + tm * 16;
                afr[tm][0] = As[(rb + gid)     * P + ko + tig];
                afr[tm][1] = As[(rb + gid + 8) * P + ko + tig];
                afr[tm][2] = As[(rb + gid)     * P + ko + tig + 4];
                afr[tm][3] = As[(rb + gid + 8) * P + ko + tig + 4];
            }
#pragma unroll
            for (int tn = 0; tn < 8; tn++) {
                const int nr = warp_n * 64 + tn * 8 + gid;
                const uint32_t b0 = Ws[nr * P + ko + tig];
                const uint32_t b1 = Ws[nr * P + ko + tig + 4];
                mma_f16(acc[0][tn], afr[0], b0, b1);
                mma_f16(acc[1][tn], afr[1], b0, b1);
            }
        }

        if (pf) {
#pragma unroll
            for (int i = 0; i < 2; i++) {
                uint4 o;
                o.x = pack_h2(fmaxf(s4[i][0].x + t4[i][0].x, 0.0f),
                              fmaxf(s4[i][0].y + t4[i][0].y, 0.0f));
                o.y = pack_h2(fmaxf(s4[i][0].z + t4[i][0].z, 0.0f),
                              fmaxf(s4[i][0].w + t4[i][0].w, 0.0f));
                o.z = pack_h2(fmaxf(s4[i][1].x + t4[i][1].x, 0.0f),
                              fmaxf(s4[i][1].y + t4[i][1].y, 0.0f));
                o.w = pack_h2(fmaxf(s4[i][1].z + t4[i][1].z, 0.0f),
                              fmaxf(s4[i][1].w + t4[i][1].w, 0.0f));
                *(uint4*)(As_[nxt] + a_sts[i]) = o;
            }
            cp_wait_all();
        }
        __syncthreads();
    }

    // ---- Epilogue: registers -> global with bias ----
    const int mbase = mt * MT + warp_m * 32;
    const int nbase = nt * NT + warp_n * 64;
#pragma unroll
    for (int tn = 0; tn < 8; tn++) {
        const int c = nbase + tn * 8 + 2 * tig;
        const float2 bz = *(const float2*)(bias + c);
#pragma unroll
        for (int tm = 0; tm < 2; tm++) {
            const int r0 = mbase + tm * 16 + gid;
            float2 v0, v1;
            v0.x = acc[tm][tn][0] + bz.x;  v0.y = acc[tm][tn][1] + bz.y;
            v1.x = acc[tm][tn][2] + bz.x;  v1.y = acc[tm][tn][3] + bz.y;
            *(float2*)(out + (size_t)r0 * Vn + c) = v0;
            *(float2*)(out + (size_t)(r0 + 8) * Vn + c) = v1;
        }
    }
}

// Pass-through lengths if the harness concatenates the output tuple.
__global__ void tail_kernel(const int* __restrict__ sl, const int* __restrict__ tl,
                            float* __restrict__ dst, int n) {
    int i = threadIdx.x;
    if (i < n) {
        float v = 0.0f;
        if (i < 8) v = (float)sl[i];
        else if (i < 16) v = (float)tl[i - 8];
        dst[i] = v;
    }
}

extern "C" void kernel_launch(void* const* d_in, const int* in_sizes, int n_in,
                              void* d_out, int out_size) {
    const float* src  = (const float*)d_in[0];   // (B,T,D) f32
    const int*   slen = (const int*)d_in[1];     // (B,) i32
    const float* tgt  = (const float*)d_in[2];   // (B,U,D) f32
    const int*   tlen = (const int*)d_in[3];     // (B,) i32
    const float* W    = (const float*)d_in[4];   // (V,D) f32
    const float* bias = (const float*)d_in[5];   // (V,) f32
    float* out = (float*)d_out;

    (void)in_sizes; (void)n_in;

    // 1) Pack W -> half2 in blocked layout (~3 MB traffic)
    prep_w_kernel<<<(Vn * Dn / 2 + 255) / 256, 256>>>(W);

    // 2) Fused relu-add GEMM (mma.sync m16n8k16 fp16, fp32 accumulate)
    cudaFuncSetAttribute(joiner_mma_kernel, cudaFuncAttributeMaxDynamicSharedMemorySize,
                         SMEM_TOTAL);
    dim3 grid(MTILES, NTILES);
    joiner_mma_kernel<<<grid, 256, SMEM_TOTAL>>>(src, tgt, bias, out);

    // 3) Optional pass-through lengths
    int extra = out_size - MAIN_OUT;
    if (extra > 0) {
        if (extra > 32) extra = 32;
        tail_kernel<<<1, 32>>>(slen, tlen, out + MAIN_OUT, extra);
    }
}

// round 15
// speedup vs baseline: 2.8442x; 1.0971x over previous
#include <cuda_runtime.h>
#include <cuda_fp16.h>
#include <cstdint>

// Problem dims
static constexpr int Bn = 8, Tn = 256, Un = 64, Dn = 512, Vn = 1024;
// Tiling
static constexpr int MT = 128;             // CTA m-tile
static constexpr int NT = 128;             // CTA n-tile
static constexpr int KC = 32;              // k-chunk (elements)
static constexpr int KP = KC / 2;          // 16 half2 pairs per row-chunk
static constexpr int NKC = Dn / KC;        // 16
static constexpr int M_TOTAL = Bn * Tn * Un;        // 131072
static constexpr int MTILES  = M_TOTAL / MT;        // 1024
static constexpr int NTILES  = Vn / NT;             // 8
static constexpr int MAIN_OUT = M_TOTAL * Vn;       // 134217728

static constexpr int NTHREADS = 128;       // 4 warps, each owns a 64x64 sub-tile

// Smem row stride in u32 (half2) units: 20 -> 80B rows, 16B aligned.
// Fragment loads: bank = (20*row + col) % 32; over a warp (rowsel=gid, col=tig[+4])
// 20*gid mod 32 = {0,20,8,28,16,4,24,12} + tig -> 32 distinct banks.
static constexpr int P = 20;
static constexpr int BUF_U = 128 * P;               // u32 per stage buffer (2560)
static constexpr int SMEM_TOTAL = 4 * BUF_U * 4;    // A0,A1,W0,W1 = 40960 B

// W pre-packed to half2, blocked [nt][kc][n(128)][kpair(16)] contiguous (1 MB).
__device__ uint32_t g_W[(size_t)NTILES * NKC * MT * KP];

// ---------------- helpers ----------------
__device__ __forceinline__ uint32_t smem_u32(const void* p) {
    uint32_t a;
    asm("{ .reg .u64 t; cvta.to.shared.u64 t, %1; cvt.u32.u64 %0, t; }" : "=r"(a) : "l"(p));
    return a;
}
__device__ __forceinline__ uint32_t pack_h2(float x, float y) {
    __half2 h = __floats2half2_rn(x, y);
    return *reinterpret_cast<uint32_t*>(&h);
}
__device__ __forceinline__ void cp_async16(uint32_t smem_addr, const void* gptr) {
    asm volatile("cp.async.cg.shared.global [%0], [%1], 16;"
                 :: "r"(smem_addr), "l"(gptr) : "memory");
}
__device__ __forceinline__ void cp_commit() {
    asm volatile("cp.async.commit_group;" ::: "memory");
}
__device__ __forceinline__ void cp_wait_all() {
    asm volatile("cp.async.wait_all;" ::: "memory");
}
// m16n8k16 fp16 MMA, fp32 accumulate. A row-major, B col-major.
__device__ __forceinline__ void mma_f16(float* d, const uint32_t* a, uint32_t b0, uint32_t b1) {
    asm volatile(
        "mma.sync.aligned.m16n8k16.row.col.f32.f16.f16.f32 "
        "{%0,%1,%2,%3}, {%4,%5,%6,%7}, {%8,%9}, {%0,%1,%2,%3};"
        : "+f"(d[0]), "+f"(d[1]), "+f"(d[2]), "+f"(d[3])
        : "r"(a[0]), "r"(a[1]), "r"(a[2]), "r"(a[3]), "r"(b0), "r"(b1));
}

// ---------------- prep kernel: W -> half2 pairs, blocked layout ----------------
__global__ void prep_w_kernel(const float* __restrict__ W) {
    int idx = blockIdx.x * blockDim.x + threadIdx.x;
    if (idx >= Vn * Dn / 2) return;
    int v = idx >> 8;          // / (Dn/2)
    int p = idx & 255;         // pair index within row
    const float2 w2 = *(const float2*)(W + (size_t)v * Dn + p * 2);
    int nt = v >> 7;           // / NT
    int n  = v & 127;
    int kc = p >> 4;           // / KP
    int kp = p & 15;
    g_W[(((size_t)nt * NKC + kc) << 11) + (n << 4) + kp] = pack_h2(w2.x, w2.y);
}

// ---------------- main kernel ----------------
__global__ __launch_bounds__(NTHREADS, 2)
void joiner_mma_kernel(const float* __restrict__ src,   // (B*T, D)
                       const float* __restrict__ tgt,   // (B*U, D)
                       const float* __restrict__ bias,  // (V,)
                       float* __restrict__ out)         // (B*T*U, V)
{
    extern __shared__ __align__(16) uint32_t smu[];
    uint32_t* As_[2] = { smu,              smu + BUF_U };
    uint32_t* Ws_[2] = { smu + 2 * BUF_U,  smu + 3 * BUF_U };

    const int tid  = threadIdx.x;
    const int wid  = tid >> 5;
    const int lane = tid & 31;
    const int gid  = lane >> 2;   // 0..7
    const int tig  = lane & 3;    // 0..3
    const int warp_m = wid & 1;   // 2 m-warps (64 rows each)
    const int warp_n = wid >> 1;  // 2 n-warps (64 cols each)

    const int mt = blockIdx.x;
    const int nt = blockIdx.y;
    const int g0 = mt * 2;        // first of two 64-row u-groups; g = flattened b*T+t
    const int bb = g0 >> 8;       // batch (T = 256)

    // Per-thread slots: A chunk = 512x16B slots, W chunk = 512x16B slots; 4 each.
    int off_src[4], off_tgt[4], a_sts[4], w_src[4];
    uint32_t w_dst[4];
#pragma unroll
    for (int i = 0; i < 4; i++) {
        const int sidx = tid + i * NTHREADS; // 0..511
        const int row  = sidx >> 2;          // 0..127
        const int seg  = sidx & 3;           // 0..3 (8 floats / 4 half2 each)
        const int g    = g0 + (row >> 6);
        const int u    = row & 63;
        off_src[i] = g * Dn + seg * 8;                 // + d0
        off_tgt[i] = (bb * Un + u) * Dn + seg * 8;     // + d0
        a_sts[i]  = row * P + seg * 4;                 // u32 index
        w_src[i]  = sidx * 4;                          // u32 index within W chunk
        w_dst[i]  = smem_u32(Ws_[0] + row * P + seg * 4);
    }
    const uint32_t wstage_bytes = BUF_U * 4;

    float acc[4][8][4];
#pragma unroll
    for (int a = 0; a < 4; a++)
#pragma unroll
        for (int b = 0; b < 8; b++)
#pragma unroll
            for (int c = 0; c < 4; c++) acc[a][b][c] = 0.0f;

    const size_t wchunk_base = ((size_t)nt * NKC) << 11;   // u32 idx of (nt, kc=0)

    // ---- Prologue: stage 0 for chunk 0 ----
#pragma unroll
    for (int i = 0; i < 4; i++)
        cp_async16(w_dst[i], g_W + wchunk_base + w_src[i]);
    cp_commit();
#pragma unroll
    for (int i = 0; i < 4; i++) {
        const float4 s0 = *(const float4*)(src + off_src[i]);
        const float4 s1 = *(const float4*)(src + off_src[i] + 4);
        const float4 t0 = *(const float4*)(tgt + off_tgt[i]);
        const float4 t1 = *(const float4*)(tgt + off_tgt[i] + 4);
        uint4 o;
        o.x = pack_h2(fmaxf(s0.x + t0.x, 0.0f), fmaxf(s0.y + t0.y, 0.0f));
        o.y = pack_h2(fmaxf(s0.z + t0.z, 0.0f), fmaxf(s0.w + t0.w, 0.0f));
        o.z = pack_h2(fmaxf(s1.x + t1.x, 0.0f), fmaxf(s1.y + t1.y, 0.0f));
        o.w = pack_h2(fmaxf(s1.z + t1.z, 0.0f), fmaxf(s1.w + t1.w, 0.0f));
        *(uint4*)(As_[0] + a_sts[i]) = o;
    }
    cp_wait_all();
    __syncthreads();

    // ---- Main loop over 16 k-chunks, double buffered ----
#pragma unroll 1
    for (int kc = 0; kc < NKC; kc++) {
        const int cur = kc & 1;
        const int nxt = cur ^ 1;
        const bool pf = (kc + 1) < NKC;

        // Prefetch next chunk: W via cp.async, A operands into registers.
        float4 s4[4][2], t4[4][2];
        if (pf) {
            const size_t wb = wchunk_base + ((size_t)(kc + 1) << 11);
#pragma unroll
            for (int i = 0; i < 4; i++)
                cp_async16(w_dst[i] + nxt * wstage_bytes, g_W + wb + w_src[i]);
            cp_commit();
            const int d0 = (kc + 1) * KC;
#pragma unroll
            for (int i = 0; i < 4; i++) {
                s4[i][0] = *(const float4*)(src + off_src[i] + d0);
                s4[i][1] = *(const float4*)(src + off_src[i] + d0 + 4);
                t4[i][0] = *(const float4*)(tgt + off_tgt[i] + d0);
                t4[i][1] = *(const float4*)(tgt + off_tgt[i] + d0 + 4);
            }
        }

        // ---- Compute: 64 MMA, 32 A-LDS, 32 B-LDS per warp (all conflict-free) ----
        const uint32_t* As = As_[cur];
        const uint32_t* Ws = Ws_[cur];
#pragma unroll
        for (int ks = 0; ks < 2; ks++) {       // two k16 steps per 32-k chunk
            const int ko = ks * 8;             // pair-column base
            uint32_t afr[4][4];
#pragma unroll
            for (int tm = 0; tm < 4; tm++) {
                const int rb = warp_m * 64 + tm * 16;
                afr[tm][0] = As[(rb + gid)     * P + ko + tig];
                afr[tm][1] = As[(rb + gid + 8) * P + ko + tig];
                afr[tm][2] = As[(rb + gid)     * P + ko + tig + 4];
                afr[tm][3] = As[(rb + gid + 8) * P + ko + tig + 4];
            }
#pragma unroll
            for (int tn = 0; tn < 8; tn++) {
                const int nr = warp_n * 64 + tn * 8 + gid;
                const uint32_t b0 = Ws[nr * P + ko + tig];
                const uint32_t b1 = Ws[nr * P + ko + tig + 4];
                mma_f16(acc[0][tn], afr[0], b0, b1);
                mma_f16(acc[1][tn], afr[1], b0, b1);
                mma_f16(acc[2][tn], afr[2], b0, b1);
                mma_f16(acc[3][tn], afr[3], b0, b1);
            }
        }

        if (pf) {
#pragma unroll
            for (int i = 0; i < 4; i++) {
                uint4 o;
                o.x = pack_h2(fmaxf(s4[i][0].x + t4[i][0].x, 0.0f),
                              fmaxf(s4[i][0].y + t4[i][0].y, 0.0f));
                o.y = pack_h2(fmaxf(s4[i][0].z + t4[i][0].z, 0.0f),
                              fmaxf(s4[i][0].w + t4[i][0].w, 0.0f));
                o.z = pack_h2(fmaxf(s4[i][1].x + t4[i][1].x, 0.0f),
                              fmaxf(s4[i][1].y + t4[i][1].y, 0.0f));
                o.w = pack_h2(fmaxf(s4[i][1].z + t4[i][1].z, 0.0f),
                              fmaxf(s4[i][1].w + t4[i][1].w, 0.0f));
                *(uint4*)(As_[nxt] + a_sts[i]) = o;
            }
            cp_wait_all();
        }
        __syncthreads();
    }

    // ---- Epilogue: registers -> global with bias ----
    const int mbase = mt * MT + warp_m * 64;
    const int nbase = nt * NT + warp_n * 64;
#pragma unroll
    for (int tn = 0; tn < 8; tn++) {
        const int c = nbase + tn * 8 + 2 * tig;
        const float2 bz = *(const float2*)(bias + c);
#pragma unroll
        for (int tm = 0; tm < 4; tm++) {
            const int r0 = mbase + tm * 16 + gid;
            float2 v0, v1;
            v0.x = acc[tm][tn][0] + bz.x;  v0.y = acc[tm][tn][1] + bz.y;
            v1.x = acc[tm][tn][2] + bz.x;  v1.y = acc[tm][tn][3] + bz.y;
            *(float2*)(out + (size_t)r0 * Vn + c) = v0;
            *(float2*)(out + (size_t)(r0 + 8) * Vn + c) = v1;
        }
    }
}

// Pass-through lengths if the harness concatenates the output tuple.
__global__ void tail_kernel(const int* __restrict__ sl, const int* __restrict__ tl,
                            float* __restrict__ dst, int n) {
    int i = threadIdx.x;
    if (i < n) {
        float v = 0.0f;
        if (i < 8) v = (float)sl[i];
        else if (i < 16) v = (float)tl[i - 8];
        dst[i] = v;
    }
}

extern "C" void kernel_launch(void* const* d_in, const int* in_sizes, int n_in,
                              void* d_out, int out_size) {
    const float* src  = (const float*)d_in[0];   // (B,T,D) f32
    const int*   slen = (const int*)d_in[1];     // (B,) i32
    const float* tgt  = (const float*)d_in[2];   // (B,U,D) f32
    const int*   tlen = (const int*)d_in[3];     // (B,) i32
    const float* W    = (const float*)d_in[4];   // (V,D) f32
    const float* bias = (const float*)d_in[5];   // (V,) f32
    float* out = (float*)d_out;

    (void)in_sizes; (void)n_in;

    // 1) Pack W -> half2 in blocked layout (~3 MB traffic)
    prep_w_kernel<<<(Vn * Dn / 2 + 255) / 256, 256>>>(W);

    // 2) Fused relu-add GEMM (mma.sync m16n8k16 fp16, fp32 accumulate, 64x64 warp tiles)
    cudaFuncSetAttribute(joiner_mma_kernel, cudaFuncAttributeMaxDynamicSharedMemorySize,
                         SMEM_TOTAL);
    dim3 grid(MTILES, NTILES);
    joiner_mma_kernel<<<grid, NTHREADS, SMEM_TOTAL>>>(src, tgt, bias, out);

    // 3) Optional pass-through lengths
    int extra = out_size - MAIN_OUT;
    if (extra > 0) {
        if (extra > 32) extra = 32;
        tail_kernel<<<1, 32>>>(slen, tlen, out + MAIN_OUT, extra);
    }
}